// round 4
// baseline (speedup 1.0000x reference)
#include <cuda_runtime.h>

#define DEV_INLINE __device__ __forceinline__

namespace {
constexpr int Bb = 8, N_ = 196, D_ = 128, DFF_ = 256, C_ = 1000;
constexpr int M_ = Bb * N_;            // 1568 total rows
constexpr float NEG = -1e30f;
}

__device__ float g_h[M_ * D_];
__device__ float g_xn[M_ * D_];
__device__ float g_q[M_ * D_];
__device__ float g_k[M_ * D_];
__device__ float g_vt[Bb * D_ * N_];   // v transposed per batch: [b][d][n]
__device__ float g_sc[Bb * N_ * N_];   // attention scores
__device__ float g_ff[M_ * DFF_];
__device__ float g_pool[Bb * D_];

DEV_INLINE float warpMax(float v) {
#pragma unroll
    for (int m = 16; m > 0; m >>= 1)
        v = fmaxf(v, __shfl_xor_sync(0xffffffffu, v, m));
    return v;
}

// ============================================================
// Split-K2 GEMM: out[m,n] = max_k(A[m,k]+W[n,k]), K=128.
// 512 threads = 2 groups of 256; group g covers K-half g.
// BM=32, BN=64, BK=32, per-thread 2x4. Partials combined via smem.
// MODE 0: qkv fused (A=g_xn, N=384 -> q|k|vt)
// MODE 1: scores per batch (A=q[b], W=k[b], M=N=196, guards)
// MODE 2: ff1 (A=g_xn, W 256x128, tau fused)
// ============================================================
template <int MODE>
__global__ void __launch_bounds__(512) gemmA_kernel(
    const float* __restrict__ W0, const float* __restrict__ W1,
    const float* __restrict__ W2, const float* __restrict__ tau) {
    __shared__ __align__(16) float As[2][32][36];
    __shared__ __align__(16) float Ws[2][32][68];
    __shared__ float red[32][68];
    const int tid = threadIdx.x;
    const int wg = tid >> 8;
    const int wtid = tid & 255;
    const int m0 = blockIdx.x * 32;
    const int n0 = blockIdx.y * 64;

    const float* Ap;
    const float* Wp;
    if (MODE == 0) {
        Ap = g_xn;
        int sec = n0 >> 7;
        Wp = (sec == 0 ? W0 : (sec == 1 ? W1 : W2)) + (n0 & 127) * 128;
    } else if (MODE == 1) {
        int b = blockIdx.z;
        Ap = g_q + b * N_ * D_;
        Wp = g_k + b * N_ * D_;
    } else {
        Ap = g_xn;
        Wp = W0 + n0 * 128;
    }

    const int kq = wtid & 7, l = wtid >> 3;
    float acc[2][4];
#pragma unroll
    for (int r = 0; r < 2; r++)
#pragma unroll
        for (int c = 0; c < 4; c++) acc[r][c] = NEG;
    const int r0 = (wtid >> 4) * 2, c0 = (wtid & 15) * 4;

#pragma unroll
    for (int t = 0; t < 2; t++) {
        int k0 = wg * 64 + t * 32;
        // A tile 32x32
        float4 av;
        if (MODE == 1 && (m0 + l) >= N_) av = make_float4(NEG, NEG, NEG, NEG);
        else av = *(const float4*)(Ap + (m0 + l) * 128 + k0 + kq * 4);
        As[wg][kq * 4 + 0][l] = av.x; As[wg][kq * 4 + 1][l] = av.y;
        As[wg][kq * 4 + 2][l] = av.z; As[wg][kq * 4 + 3][l] = av.w;
        // W tile 64x32
#pragma unroll
        for (int p = 0; p < 2; p++) {
            int nl = l + p * 32;
            float4 wv;
            if (MODE == 1 && (n0 + nl) >= N_) wv = make_float4(NEG, NEG, NEG, NEG);
            else {
                int wrow = (MODE == 1) ? (n0 + nl) : nl;
                wv = *(const float4*)(Wp + wrow * 128 + k0 + kq * 4);
            }
            Ws[wg][kq * 4 + 0][nl] = wv.x; Ws[wg][kq * 4 + 1][nl] = wv.y;
            Ws[wg][kq * 4 + 2][nl] = wv.z; Ws[wg][kq * 4 + 3][nl] = wv.w;
        }
        __syncthreads();
#pragma unroll
        for (int kk = 0; kk < 32; kk++) {
            float a0 = As[wg][kk][r0], a1 = As[wg][kk][r0 + 1];
            float4 w = *(const float4*)&Ws[wg][kk][c0];
            acc[0][0] = fmaxf(acc[0][0], a0 + w.x);
            acc[0][1] = fmaxf(acc[0][1], a0 + w.y);
            acc[0][2] = fmaxf(acc[0][2], a0 + w.z);
            acc[0][3] = fmaxf(acc[0][3], a0 + w.w);
            acc[1][0] = fmaxf(acc[1][0], a1 + w.x);
            acc[1][1] = fmaxf(acc[1][1], a1 + w.y);
            acc[1][2] = fmaxf(acc[1][2], a1 + w.z);
            acc[1][3] = fmaxf(acc[1][3], a1 + w.w);
        }
        __syncthreads();
    }

    if (wg == 1) {
#pragma unroll
        for (int r = 0; r < 2; r++)
#pragma unroll
            for (int c = 0; c < 4; c++) red[r0 + r][c0 + c] = acc[r][c];
    }
    __syncthreads();
    if (wg == 1) return;

#pragma unroll
    for (int r = 0; r < 2; r++)
#pragma unroll
        for (int c = 0; c < 4; c++)
            acc[r][c] = fmaxf(acc[r][c], red[r0 + r][c0 + c]);

    if (MODE == 0) {
#pragma unroll
        for (int r = 0; r < 2; r++) {
            int gm = m0 + r0 + r;
            int b = gm / 196, i = gm - b * 196;
#pragma unroll
            for (int c = 0; c < 4; c++) {
                int gn = n0 + c0 + c;
                float v = acc[r][c];
                if (gn < 128)       g_q[gm * 128 + gn] = v;
                else if (gn < 256)  g_k[gm * 128 + (gn - 128)] = v;
                else                g_vt[(b * 128 + (gn - 256)) * N_ + i] = v;
            }
        }
    } else if (MODE == 1) {
        int b = blockIdx.z;
        float* out = g_sc + b * N_ * N_;
#pragma unroll
        for (int r = 0; r < 2; r++) {
            int i = m0 + r0 + r;
            if (i < N_) {
#pragma unroll
                for (int c = 0; c < 4; c++) {
                    int j = n0 + c0 + c;
                    if (j < N_) out[i * N_ + j] = acc[r][c];
                }
            }
        }
    } else {
        float tv = tau[0];
#pragma unroll
        for (int r = 0; r < 2; r++) {
            int gm = m0 + r0 + r;
#pragma unroll
            for (int c = 0; c < 4; c++)
                g_ff[gm * 256 + n0 + c0 + c] = fmaxf(acc[r][c], tv);
        }
    }
}

// ============================================================
// Row-fused config: BM=8, BN=128, split-K2, 512 threads.
// Group g = 256 threads; warp w (0..7) owns output row w fully
// (lane -> 4 cols). Inner: broadcast-A 1x4.
// ============================================================
DEV_INLINE void inner8(const float (&As)[32][12], const float (&Ws)[32][132],
                       float (&acc)[4], int w, int c0) {
#pragma unroll
    for (int kk = 0; kk < 32; kk++) {
        float a = As[kk][w];
        float4 wv = *(const float4*)&Ws[kk][c0];
        acc[0] = fmaxf(acc[0], a + wv.x);
        acc[1] = fmaxf(acc[1], a + wv.y);
        acc[2] = fmaxf(acc[2], a + wv.z);
        acc[3] = fmaxf(acc[3], a + wv.w);
    }
}
DEV_INLINE void inner8rm(const float (&As)[32][12], const float (&Ws)[32][132],
                         float (&acc)[4], float& rm, int w, int c0) {
#pragma unroll
    for (int kk = 0; kk < 32; kk++) {
        float a = As[kk][w];
        rm = fmaxf(rm, a);
        float4 wv = *(const float4*)&Ws[kk][c0];
        acc[0] = fmaxf(acc[0], a + wv.x);
        acc[1] = fmaxf(acc[1], a + wv.y);
        acc[2] = fmaxf(acc[2], a + wv.z);
        acc[3] = fmaxf(acc[3], a + wv.w);
    }
}

// embed: patchify + trop_mm(embed_W) + pos + pnorm -> g_h, g_xn. K=256.
__global__ void __launch_bounds__(512) embed_kernel(
    const float* __restrict__ x, const float* __restrict__ eW,
    const float* __restrict__ pos) {
    __shared__ __align__(16) float As[2][32][12];
    __shared__ __align__(16) float Ws[2][32][132];
    __shared__ float red[8][132];
    const int tid = threadIdx.x;
    const int wg = tid >> 8;
    const int wtid = tid & 255;
    const int m0 = blockIdx.x * 8;
    const int w = wtid >> 5, lane = wtid & 31, c0 = lane * 4;
    float acc[4] = {NEG, NEG, NEG, NEG};

#pragma unroll
    for (int t = 0; t < 4; t++) {
        int k0 = wg * 128 + t * 32;
        if (wtid < 64) {
            int row = wtid >> 3, kq = wtid & 7;
            int gm = m0 + row;
            int b = gm / 196, n = gm - b * 196;
            int gy = n / 14, gx = n - gy * 14;
            int k = k0 + kq * 4;
            int py = k >> 4, px = k & 15;
            float4 av = *(const float4*)(x + b * 50176 + (gy * 16 + py) * 224 + gx * 16 + px);
            As[wg][kq * 4 + 0][row] = av.x; As[wg][kq * 4 + 1][row] = av.y;
            As[wg][kq * 4 + 2][row] = av.z; As[wg][kq * 4 + 3][row] = av.w;
        }
        {
            int kq = wtid & 7, base = wtid >> 3;
#pragma unroll
            for (int p = 0; p < 4; p++) {
                int nl = base + p * 32;
                float4 wv = *(const float4*)(eW + nl * 256 + k0 + kq * 4);
                Ws[wg][kq * 4 + 0][nl] = wv.x; Ws[wg][kq * 4 + 1][nl] = wv.y;
                Ws[wg][kq * 4 + 2][nl] = wv.z; Ws[wg][kq * 4 + 3][nl] = wv.w;
            }
        }
        __syncthreads();
        inner8(As[wg], Ws[wg], acc, w, c0);
        __syncthreads();
    }

    if (wg == 1) {
#pragma unroll
        for (int c = 0; c < 4; c++) red[w][c0 + c] = acc[c];
    }
    __syncthreads();
    if (wg == 1) return;

    int gm = m0 + w;
    int n = gm % 196;
    float h[4];
#pragma unroll
    for (int c = 0; c < 4; c++)
        h[c] = fmaxf(acc[c], red[w][c0 + c]) + pos[n * 128 + c0 + c];
    float dm = warpMax(fmaxf(fmaxf(h[0], h[1]), fmaxf(h[2], h[3])));
    int base = gm * 128 + c0;
#pragma unroll
    for (int c = 0; c < 4; c++) {
        g_h[base + c] = h[c];
        g_xn[base + c] = h[c] - dm;
    }
}

// attnout: o[i,d]=max_j(sc[i,j]+vt[d,j])-rowmax; pnorm; residual; pnorm.
// K=196: group g takes tiles j0 = t*64+g*32 (t=0..3); j0=224 is a dummy.
__global__ void __launch_bounds__(512) attnout_kernel() {
    __shared__ __align__(16) float As[2][32][12];
    __shared__ __align__(16) float Ws[2][32][132];
    __shared__ float red[8][132];
    __shared__ float redrm[8];
    const int tid = threadIdx.x;
    const int wg = tid >> 8;
    const int wtid = tid & 255;
    const int b = blockIdx.y;
    const int m0 = blockIdx.x * 8;
    const float* Ap = g_sc + b * N_ * N_;
    const float* Vp = g_vt + b * D_ * N_;
    const int w = wtid >> 5, lane = wtid & 31, c0 = lane * 4;
    float acc[4] = {NEG, NEG, NEG, NEG};
    float rm = NEG;

#pragma unroll
    for (int t = 0; t < 4; t++) {
        int j0 = t * 64 + wg * 32;
        bool tvalid = j0 < N_;
        if (tvalid) {
            if (wtid < 64) {
                int row = wtid >> 3, kq = wtid & 7;
                int gm = m0 + row;
                int j = j0 + kq * 4;
                float4 av;
                if (gm < N_ && j + 3 < N_) av = *(const float4*)(Ap + gm * N_ + j);
                else if (gm < N_) av = make_float4(
                        (j + 0 < N_) ? Ap[gm * N_ + j + 0] : NEG,
                        (j + 1 < N_) ? Ap[gm * N_ + j + 1] : NEG,
                        (j + 2 < N_) ? Ap[gm * N_ + j + 2] : NEG,
                        (j + 3 < N_) ? Ap[gm * N_ + j + 3] : NEG);
                else av = make_float4(NEG, NEG, NEG, NEG);
                As[wg][kq * 4 + 0][row] = av.x; As[wg][kq * 4 + 1][row] = av.y;
                As[wg][kq * 4 + 2][row] = av.z; As[wg][kq * 4 + 3][row] = av.w;
            }
            {
                int kq = wtid & 7, base = wtid >> 3;
                int j = j0 + kq * 4;
#pragma unroll
                for (int p = 0; p < 4; p++) {
                    int d = base + p * 32;
                    float4 vv;
                    if (j + 3 < N_) vv = *(const float4*)(Vp + d * N_ + j);
                    else vv = make_float4(
                            (j + 0 < N_) ? Vp[d * N_ + j + 0] : NEG,
                            (j + 1 < N_) ? Vp[d * N_ + j + 1] : NEG,
                            (j + 2 < N_) ? Vp[d * N_ + j + 2] : NEG,
                            (j + 3 < N_) ? Vp[d * N_ + j + 3] : NEG);
                    Ws[wg][kq * 4 + 0][d] = vv.x; Ws[wg][kq * 4 + 1][d] = vv.y;
                    Ws[wg][kq * 4 + 2][d] = vv.z; Ws[wg][kq * 4 + 3][d] = vv.w;
                }
            }
        }
        __syncthreads();
        inner8rm(As[wg], Ws[wg], acc, rm, w, c0);   // dummy tile: idempotent recompute
        __syncthreads();
    }

    if (wg == 1) {
#pragma unroll
        for (int c = 0; c < 4; c++) red[w][c0 + c] = acc[c];
        if (lane == 0) redrm[w] = rm;
    }
    __syncthreads();
    if (wg == 1) return;

    int i = m0 + w;
    if (i < N_) {
        float frm = fmaxf(rm, redrm[w]);
        float o[4];
#pragma unroll
        for (int c = 0; c < 4; c++)
            o[c] = fmaxf(acc[c], red[w][c0 + c]) - frm;
        float dm = warpMax(fmaxf(fmaxf(o[0], o[1]), fmaxf(o[2], o[3])));
        int base = (b * 196 + i) * 128 + c0;
        float nx[4];
#pragma unroll
        for (int c = 0; c < 4; c++)
            nx[c] = fmaxf(g_h[base + c], o[c] - dm);
        float dm2 = warpMax(fmaxf(fmaxf(nx[0], nx[1]), fmaxf(nx[2], nx[3])));
#pragma unroll
        for (int c = 0; c < 4; c++) {
            g_h[base + c] = nx[c];
            g_xn[base + c] = nx[c] - dm2;
        }
    }
}

// ff2: trop_mm(g_ff, f2W), K=256; pnorm; residual; pnorm.
__global__ void __launch_bounds__(512) ff2_kernel(const float* __restrict__ W) {
    __shared__ __align__(16) float As[2][32][12];
    __shared__ __align__(16) float Ws[2][32][132];
    __shared__ float red[8][132];
    const int tid = threadIdx.x;
    const int wg = tid >> 8;
    const int wtid = tid & 255;
    const int m0 = blockIdx.x * 8;
    const int w = wtid >> 5, lane = wtid & 31, c0 = lane * 4;
    float acc[4] = {NEG, NEG, NEG, NEG};

#pragma unroll
    for (int t = 0; t < 4; t++) {
        int k0 = wg * 128 + t * 32;
        if (wtid < 64) {
            int row = wtid >> 3, kq = wtid & 7;
            float4 av = *(const float4*)(g_ff + (m0 + row) * 256 + k0 + kq * 4);
            As[wg][kq * 4 + 0][row] = av.x; As[wg][kq * 4 + 1][row] = av.y;
            As[wg][kq * 4 + 2][row] = av.z; As[wg][kq * 4 + 3][row] = av.w;
        }
        {
            int kq = wtid & 7, base = wtid >> 3;
#pragma unroll
            for (int p = 0; p < 4; p++) {
                int nl = base + p * 32;
                float4 wv = *(const float4*)(W + nl * 256 + k0 + kq * 4);
                Ws[wg][kq * 4 + 0][nl] = wv.x; Ws[wg][kq * 4 + 1][nl] = wv.y;
                Ws[wg][kq * 4 + 2][nl] = wv.z; Ws[wg][kq * 4 + 3][nl] = wv.w;
            }
        }
        __syncthreads();
        inner8(As[wg], Ws[wg], acc, w, c0);
        __syncthreads();
    }

    if (wg == 1) {
#pragma unroll
        for (int c = 0; c < 4; c++) red[w][c0 + c] = acc[c];
    }
    __syncthreads();
    if (wg == 1) return;

    int gm = m0 + w;
#pragma unroll
    for (int c = 0; c < 4; c++) acc[c] = fmaxf(acc[c], red[w][c0 + c]);
    float dm = warpMax(fmaxf(fmaxf(acc[0], acc[1]), fmaxf(acc[2], acc[3])));
    int base = gm * 128 + c0;
    float nx[4];
#pragma unroll
    for (int c = 0; c < 4; c++)
        nx[c] = fmaxf(g_h[base + c], acc[c] - dm);
    float dm2 = warpMax(fmaxf(fmaxf(nx[0], nx[1]), fmaxf(nx[2], nx[3])));
#pragma unroll
    for (int c = 0; c < 4; c++) {
        g_h[base + c] = nx[c];
        g_xn[base + c] = nx[c] - dm2;
    }
}

__global__ void __launch_bounds__(512) pool_kernel() {
    __shared__ float sm[4][128];
    int b = blockIdx.x;
    int d = threadIdx.x & 127;
    int q = threadIdx.x >> 7;
    float m = NEG;
    for (int n = q; n < N_; n += 4)
        m = fmaxf(m, g_h[(b * N_ + n) * D_ + d]);
    sm[q][d] = m;
    __syncthreads();
    if (q == 0) {
        m = fmaxf(fmaxf(sm[0][d], sm[1][d]), fmaxf(sm[2][d], sm[3][d]));
        g_pool[b * D_ + d] = m;
    }
}

__global__ void __launch_bounds__(256) head_kernel(
    const float* __restrict__ hW, const float* __restrict__ ls,
    float* __restrict__ out) {
    __shared__ float sp[128];
    const int b = blockIdx.y;
    const int tid = threadIdx.x;
    if (tid < 128) sp[tid] = g_pool[b * 128 + tid];
    __syncthreads();
    int c = blockIdx.x * 256 + tid;
    if (c < C_) {
        float acc = NEG;
#pragma unroll 8
        for (int d = 0; d < 128; d += 4) {
            float4 w = *(const float4*)(hW + c * 128 + d);
            acc = fmaxf(acc, sp[d + 0] + w.x);
            acc = fmaxf(acc, sp[d + 1] + w.y);
            acc = fmaxf(acc, sp[d + 2] + w.z);
            acc = fmaxf(acc, sp[d + 3] + w.w);
        }
        out[b * C_ + c] = acc * ls[0];
    }
}

extern "C" void kernel_launch(void* const* d_in, const int* in_sizes, int n_in,
                              void* d_out, int out_size) {
    const float* x   = (const float*)d_in[0];
    const float* eW  = (const float*)d_in[1];
    const float* pos = (const float*)d_in[2];
    const float* qW[2]  = {(const float*)d_in[3],  (const float*)d_in[9]};
    const float* kW[2]  = {(const float*)d_in[4],  (const float*)d_in[10]};
    const float* vW[2]  = {(const float*)d_in[5],  (const float*)d_in[11]};
    const float* f1[2]  = {(const float*)d_in[6],  (const float*)d_in[12]};
    const float* f2[2]  = {(const float*)d_in[7],  (const float*)d_in[13]};
    const float* tau[2] = {(const float*)d_in[8],  (const float*)d_in[14]};
    const float* hW = (const float*)d_in[15];
    const float* ls = (const float*)d_in[16];
    float* out = (float*)d_out;

    embed_kernel<<<196, 512>>>(x, eW, pos);
    for (int l = 0; l < 2; l++) {
        gemmA_kernel<0><<<dim3(49, 6), 512>>>(qW[l], kW[l], vW[l], nullptr);
        gemmA_kernel<1><<<dim3(7, 4, 8), 512>>>(nullptr, nullptr, nullptr, nullptr);
        attnout_kernel<<<dim3(25, 8), 512>>>();
        gemmA_kernel<2><<<dim3(49, 4), 512>>>(f1[l], nullptr, nullptr, tau[l]);
        ff2_kernel<<<196, 512>>>(f2[l]);
    }
    pool_kernel<<<8, 512>>>();
    head_kernel<<<dim3(4, 8), 256>>>(hW, ls, out);
}

// round 5
// speedup vs baseline: 1.2547x; 1.2547x over previous
#include <cuda_runtime.h>

#define DEV_INLINE __device__ __forceinline__

namespace {
constexpr int Bb = 8, N_ = 196, D_ = 128, DFF_ = 256, C_ = 1000;
constexpr int M_ = Bb * N_;            // 1568 total rows
constexpr float NEG = -1e30f;
}

__device__ float g_h[M_ * D_];
__device__ float g_xn[M_ * D_];
__device__ float g_q[M_ * D_];
__device__ float g_k[M_ * D_];
__device__ float g_vt[Bb * D_ * N_];   // v transposed per batch: [b][d][n]
__device__ float g_sc[Bb * N_ * N_];   // attention scores
__device__ float g_ff[M_ * DFF_];
__device__ float g_pool[Bb * D_];

DEV_INLINE float warpMax(float v) {
#pragma unroll
    for (int m = 16; m > 0; m >>= 1)
        v = fmaxf(v, __shfl_xor_sync(0xffffffffu, v, m));
    return v;
}

// ============================================================
// GEMM: out[m,n] = max_k(A[m,k] + W[n,k]), K=128.
// BM=32, BN=64, BK=32, **128 threads**, per-thread 4x4
// (2 LDS.128 feed 32 math ops; 16 independent chains).
// MODE 0: qkv fused (A=g_xn, N=384 -> q|k|vt)
// MODE 1: scores per batch (A=q[b], W=k[b], M=N=196, guards)
// MODE 2: ff1 (A=g_xn, W 256x128, tau fused)
// ============================================================
template <int MODE>
__global__ void __launch_bounds__(128) gemmA_kernel(
    const float* __restrict__ W0, const float* __restrict__ W1,
    const float* __restrict__ W2, const float* __restrict__ tau) {
    __shared__ __align__(16) float As[32][36];
    __shared__ __align__(16) float Ws[32][68];
    const int tid = threadIdx.x;
    const int m0 = blockIdx.x * 32;
    const int n0 = blockIdx.y * 64;

    const float* Ap;
    const float* Wp;
    if (MODE == 0) {
        Ap = g_xn;
        int sec = n0 >> 7;
        Wp = (sec == 0 ? W0 : (sec == 1 ? W1 : W2)) + (n0 & 127) * 128;
    } else if (MODE == 1) {
        int b = blockIdx.z;
        Ap = g_q + b * N_ * D_;
        Wp = g_k + b * N_ * D_;
    } else {
        Ap = g_xn;
        Wp = W0 + n0 * 128;
    }

    const int kq = tid & 7, l = tid >> 3;   // loader: 8 quads x 16 rows
    float acc[4][4];
#pragma unroll
    for (int r = 0; r < 4; r++)
#pragma unroll
        for (int c = 0; c < 4; c++) acc[r][c] = NEG;

    const int r0 = (tid >> 4) * 4, c0 = (tid & 15) * 4;

#pragma unroll
    for (int k0 = 0; k0 < 128; k0 += 32) {
        // A tile 32x32 (rows l, l+16)
#pragma unroll
        for (int p = 0; p < 2; p++) {
            int row = l + p * 16;
            float4 av;
            if (MODE == 1 && (m0 + row) >= N_) av = make_float4(NEG, NEG, NEG, NEG);
            else av = *(const float4*)(Ap + (m0 + row) * 128 + k0 + kq * 4);
            As[kq * 4 + 0][row] = av.x; As[kq * 4 + 1][row] = av.y;
            As[kq * 4 + 2][row] = av.z; As[kq * 4 + 3][row] = av.w;
        }
        // W tile 64x32 (rows l, l+16, l+32, l+48)
#pragma unroll
        for (int p = 0; p < 4; p++) {
            int nl = l + p * 16;
            float4 wv;
            if (MODE == 1 && (n0 + nl) >= N_) wv = make_float4(NEG, NEG, NEG, NEG);
            else {
                int wrow = (MODE == 1) ? (n0 + nl) : nl;
                wv = *(const float4*)(Wp + wrow * 128 + k0 + kq * 4);
            }
            Ws[kq * 4 + 0][nl] = wv.x; Ws[kq * 4 + 1][nl] = wv.y;
            Ws[kq * 4 + 2][nl] = wv.z; Ws[kq * 4 + 3][nl] = wv.w;
        }
        __syncthreads();
#pragma unroll
        for (int kk = 0; kk < 32; kk++) {
            float4 a = *(const float4*)&As[kk][r0];
            float4 w = *(const float4*)&Ws[kk][c0];
            float ar[4] = {a.x, a.y, a.z, a.w};
            float wr[4] = {w.x, w.y, w.z, w.w};
#pragma unroll
            for (int r = 0; r < 4; r++)
#pragma unroll
                for (int c = 0; c < 4; c++)
                    acc[r][c] = fmaxf(acc[r][c], ar[r] + wr[c]);
        }
        __syncthreads();
    }

    if (MODE == 0) {
#pragma unroll
        for (int r = 0; r < 4; r++) {
            int gm = m0 + r0 + r;
            int b = gm / 196, i = gm - b * 196;
#pragma unroll
            for (int c = 0; c < 4; c++) {
                int gn = n0 + c0 + c;
                float v = acc[r][c];
                if (gn < 128)       g_q[gm * 128 + gn] = v;
                else if (gn < 256)  g_k[gm * 128 + (gn - 128)] = v;
                else                g_vt[(b * 128 + (gn - 256)) * N_ + i] = v;
            }
        }
    } else if (MODE == 1) {
        int b = blockIdx.z;
        float* out = g_sc + b * N_ * N_;
#pragma unroll
        for (int r = 0; r < 4; r++) {
            int i = m0 + r0 + r;
            if (i < N_) {
#pragma unroll
                for (int c = 0; c < 4; c++) {
                    int j = n0 + c0 + c;
                    if (j < N_) out[i * N_ + j] = acc[r][c];
                }
            }
        }
    } else {
        float tv = tau[0];
#pragma unroll
        for (int r = 0; r < 4; r++) {
            int gm = m0 + r0 + r;
#pragma unroll
            for (int c = 0; c < 4; c++)
                g_ff[gm * 256 + n0 + c0 + c] = fmaxf(acc[r][c], tv);
        }
    }
}

// ============================================================
// Config B (split-K, 512 threads): BM=16, BN=128, BK=32 (R2 proven)
// ============================================================
template <bool DO_RM>
DEV_INLINE void innerB(const float (&As)[32][18], const float (&Ws)[32][132],
                       float (&acc)[2][4], float (&rm)[2], int r0, int c0) {
#pragma unroll
    for (int kk = 0; kk < 32; kk++) {
        float a0 = As[kk][r0], a1 = As[kk][r0 + 1];
        float4 w = *(const float4*)&Ws[kk][c0];
        if (DO_RM) { rm[0] = fmaxf(rm[0], a0); rm[1] = fmaxf(rm[1], a1); }
        acc[0][0] = fmaxf(acc[0][0], a0 + w.x);
        acc[0][1] = fmaxf(acc[0][1], a0 + w.y);
        acc[0][2] = fmaxf(acc[0][2], a0 + w.z);
        acc[0][3] = fmaxf(acc[0][3], a0 + w.w);
        acc[1][0] = fmaxf(acc[1][0], a1 + w.x);
        acc[1][1] = fmaxf(acc[1][1], a1 + w.y);
        acc[1][2] = fmaxf(acc[1][2], a1 + w.z);
        acc[1][3] = fmaxf(acc[1][3], a1 + w.w);
    }
}

__global__ void __launch_bounds__(512) embed_kernel(
    const float* __restrict__ x, const float* __restrict__ eW,
    const float* __restrict__ pos) {
    __shared__ __align__(16) float As[2][32][18];
    __shared__ __align__(16) float Ws[2][32][132];
    __shared__ float red[16][132];
    const int tid = threadIdx.x;
    const int wg = tid >> 8;
    const int wtid = tid & 255;
    const int m0 = blockIdx.x * 16;
    const int kq = wtid & 7, l = wtid >> 3;
    float acc[2][4];
    float rm[2];
#pragma unroll
    for (int r = 0; r < 2; r++)
#pragma unroll
        for (int c = 0; c < 4; c++) acc[r][c] = NEG;
    const int r0 = (wtid >> 5) * 2, c0 = (wtid & 31) * 4;
    const int kbase = wg * 128;

#pragma unroll
    for (int t = 0; t < 4; t++) {
        int k0 = kbase + t * 32;
        if (wtid < 128) {
            int gm = m0 + l;
            int b = gm / 196, n = gm - b * 196;
            int gy = n / 14, gx = n - gy * 14;
            int k = k0 + kq * 4;
            int py = k >> 4, px = k & 15;
            float4 av = *(const float4*)(x + b * 50176 + (gy * 16 + py) * 224 + gx * 16 + px);
            As[wg][kq * 4 + 0][l] = av.x; As[wg][kq * 4 + 1][l] = av.y;
            As[wg][kq * 4 + 2][l] = av.z; As[wg][kq * 4 + 3][l] = av.w;
        }
#pragma unroll
        for (int p = 0; p < 4; p++) {
            int nl = l + p * 32;
            float4 wv = *(const float4*)(eW + nl * 256 + k0 + kq * 4);
            Ws[wg][kq * 4 + 0][nl] = wv.x; Ws[wg][kq * 4 + 1][nl] = wv.y;
            Ws[wg][kq * 4 + 2][nl] = wv.z; Ws[wg][kq * 4 + 3][nl] = wv.w;
        }
        __syncthreads();
        innerB<false>(As[wg], Ws[wg], acc, rm, r0, c0);
        __syncthreads();
    }

    if (wg == 1) {
#pragma unroll
        for (int r = 0; r < 2; r++)
#pragma unroll
            for (int c = 0; c < 4; c++) red[r0 + r][c0 + c] = acc[r][c];
    }
    __syncthreads();
    if (wg == 1) return;

#pragma unroll
    for (int r = 0; r < 2; r++) {
        int gm = m0 + r0 + r;
        int n = gm % 196;
        float h[4];
#pragma unroll
        for (int c = 0; c < 4; c++)
            h[c] = fmaxf(acc[r][c], red[r0 + r][c0 + c]) + pos[n * 128 + c0 + c];
        float dm = warpMax(fmaxf(fmaxf(h[0], h[1]), fmaxf(h[2], h[3])));
        int base = gm * 128 + c0;
#pragma unroll
        for (int c = 0; c < 4; c++) {
            g_h[base + c] = h[c];
            g_xn[base + c] = h[c] - dm;
        }
    }
}

__global__ void __launch_bounds__(512) attnout_kernel() {
    __shared__ __align__(16) float As[2][32][18];
    __shared__ __align__(16) float Ws[2][32][132];
    __shared__ float red[16][132];
    __shared__ float redrm[16];
    const int tid = threadIdx.x;
    const int wg = tid >> 8;
    const int wtid = tid & 255;
    const int b = blockIdx.y;
    const int m0 = blockIdx.x * 16;
    const float* Ap = g_sc + b * N_ * N_;
    const float* Wp = g_vt + b * D_ * N_;
    const int kq = wtid & 7, l = wtid >> 3;
    float acc[2][4];
    float rm[2] = {NEG, NEG};
#pragma unroll
    for (int r = 0; r < 2; r++)
#pragma unroll
        for (int c = 0; c < 4; c++) acc[r][c] = NEG;
    const int r0 = (wtid >> 5) * 2, c0 = (wtid & 31) * 4;
    const int kbase = wg * 128;

#pragma unroll
    for (int t = 0; t < 4; t++) {
        int k0 = kbase + t * 32;
        bool tvalid = k0 < 196;
        bool kvalid = tvalid && (kq * 4 < 196 - k0);
        if (tvalid) {
            if (wtid < 128) {
                int gm = m0 + l;
                float4 av = (gm < N_ && kvalid)
                                ? *(const float4*)(Ap + gm * 196 + k0 + kq * 4)
                                : make_float4(NEG, NEG, NEG, NEG);
                As[wg][kq * 4 + 0][l] = av.x; As[wg][kq * 4 + 1][l] = av.y;
                As[wg][kq * 4 + 2][l] = av.z; As[wg][kq * 4 + 3][l] = av.w;
            }
#pragma unroll
            for (int p = 0; p < 4; p++) {
                int nl = l + p * 32;
                float4 wv = kvalid ? *(const float4*)(Wp + nl * 196 + k0 + kq * 4)
                                   : make_float4(NEG, NEG, NEG, NEG);
                Ws[wg][kq * 4 + 0][nl] = wv.x; Ws[wg][kq * 4 + 1][nl] = wv.y;
                Ws[wg][kq * 4 + 2][nl] = wv.z; Ws[wg][kq * 4 + 3][nl] = wv.w;
            }
        }
        __syncthreads();
        innerB<true>(As[wg], Ws[wg], acc, rm, r0, c0);
        __syncthreads();
    }

    if (wg == 1) {
#pragma unroll
        for (int r = 0; r < 2; r++) {
#pragma unroll
            for (int c = 0; c < 4; c++) red[r0 + r][c0 + c] = acc[r][c];
            if ((wtid & 31) == 0) redrm[r0 + r] = rm[r];
        }
    }
    __syncthreads();
    if (wg == 1) return;

#pragma unroll
    for (int r = 0; r < 2; r++) {
        int i = m0 + r0 + r;
        if (i < N_) {
            float frm = fmaxf(rm[r], redrm[r0 + r]);
            float o[4];
#pragma unroll
            for (int c = 0; c < 4; c++)
                o[c] = fmaxf(acc[r][c], red[r0 + r][c0 + c]) - frm;
            float dm = warpMax(fmaxf(fmaxf(o[0], o[1]), fmaxf(o[2], o[3])));
            int base = (b * 196 + i) * 128 + c0;
            float nx[4];
#pragma unroll
            for (int c = 0; c < 4; c++)
                nx[c] = fmaxf(g_h[base + c], o[c] - dm);
            float dm2 = warpMax(fmaxf(fmaxf(nx[0], nx[1]), fmaxf(nx[2], nx[3])));
#pragma unroll
            for (int c = 0; c < 4; c++) {
                g_h[base + c] = nx[c];
                g_xn[base + c] = nx[c] - dm2;
            }
        }
    }
}

__global__ void __launch_bounds__(512) ff2_kernel(const float* __restrict__ W) {
    __shared__ __align__(16) float As[2][32][18];
    __shared__ __align__(16) float Ws[2][32][132];
    __shared__ float red[16][132];
    const int tid = threadIdx.x;
    const int wg = tid >> 8;
    const int wtid = tid & 255;
    const int m0 = blockIdx.x * 16;
    const int kq = wtid & 7, l = wtid >> 3;
    float acc[2][4];
    float rm[2];
#pragma unroll
    for (int r = 0; r < 2; r++)
#pragma unroll
        for (int c = 0; c < 4; c++) acc[r][c] = NEG;
    const int r0 = (wtid >> 5) * 2, c0 = (wtid & 31) * 4;
    const int kbase = wg * 128;

#pragma unroll
    for (int t = 0; t < 4; t++) {
        int k0 = kbase + t * 32;
        if (wtid < 128) {
            float4 av = *(const float4*)(g_ff + (m0 + l) * 256 + k0 + kq * 4);
            As[wg][kq * 4 + 0][l] = av.x; As[wg][kq * 4 + 1][l] = av.y;
            As[wg][kq * 4 + 2][l] = av.z; As[wg][kq * 4 + 3][l] = av.w;
        }
#pragma unroll
        for (int p = 0; p < 4; p++) {
            int nl = l + p * 32;
            float4 wv = *(const float4*)(W + nl * 256 + k0 + kq * 4);
            Ws[wg][kq * 4 + 0][nl] = wv.x; Ws[wg][kq * 4 + 1][nl] = wv.y;
            Ws[wg][kq * 4 + 2][nl] = wv.z; Ws[wg][kq * 4 + 3][nl] = wv.w;
        }
        __syncthreads();
        innerB<false>(As[wg], Ws[wg], acc, rm, r0, c0);
        __syncthreads();
    }

    if (wg == 1) {
#pragma unroll
        for (int r = 0; r < 2; r++)
#pragma unroll
            for (int c = 0; c < 4; c++) red[r0 + r][c0 + c] = acc[r][c];
    }
    __syncthreads();
    if (wg == 1) return;

#pragma unroll
    for (int r = 0; r < 2; r++) {
        int gm = m0 + r0 + r;
#pragma unroll
        for (int c = 0; c < 4; c++)
            acc[r][c] = fmaxf(acc[r][c], red[r0 + r][c0 + c]);
        float dm = warpMax(fmaxf(fmaxf(acc[r][0], acc[r][1]), fmaxf(acc[r][2], acc[r][3])));
        int base = gm * 128 + c0;
        float nx[4];
#pragma unroll
        for (int c = 0; c < 4; c++)
            nx[c] = fmaxf(g_h[base + c], acc[r][c] - dm);
        float dm2 = warpMax(fmaxf(fmaxf(nx[0], nx[1]), fmaxf(nx[2], nx[3])));
#pragma unroll
        for (int c = 0; c < 4; c++) {
            g_h[base + c] = nx[c];
            g_xn[base + c] = nx[c] - dm2;
        }
    }
}

__global__ void __launch_bounds__(512) pool_kernel() {
    __shared__ float sm[4][128];
    int b = blockIdx.x;
    int d = threadIdx.x & 127;
    int q = threadIdx.x >> 7;
    float m = NEG;
    for (int n = q; n < N_; n += 4)
        m = fmaxf(m, g_h[(b * N_ + n) * D_ + d]);
    sm[q][d] = m;
    __syncthreads();
    if (q == 0) {
        m = fmaxf(fmaxf(sm[0][d], sm[1][d]), fmaxf(sm[2][d], sm[3][d]));
        g_pool[b * D_ + d] = m;
    }
}

__global__ void __launch_bounds__(256) head_kernel(
    const float* __restrict__ hW, const float* __restrict__ ls,
    float* __restrict__ out) {
    __shared__ float sp[128];
    const int b = blockIdx.y;
    const int tid = threadIdx.x;
    if (tid < 128) sp[tid] = g_pool[b * 128 + tid];
    __syncthreads();
    int c = blockIdx.x * 256 + tid;
    if (c < C_) {
        float acc = NEG;
#pragma unroll 8
        for (int d = 0; d < 128; d += 4) {
            float4 w = *(const float4*)(hW + c * 128 + d);
            acc = fmaxf(acc, sp[d + 0] + w.x);
            acc = fmaxf(acc, sp[d + 1] + w.y);
            acc = fmaxf(acc, sp[d + 2] + w.z);
            acc = fmaxf(acc, sp[d + 3] + w.w);
        }
        out[b * C_ + c] = acc * ls[0];
    }
}

extern "C" void kernel_launch(void* const* d_in, const int* in_sizes, int n_in,
                              void* d_out, int out_size) {
    const float* x   = (const float*)d_in[0];
    const float* eW  = (const float*)d_in[1];
    const float* pos = (const float*)d_in[2];
    const float* qW[2]  = {(const float*)d_in[3],  (const float*)d_in[9]};
    const float* kW[2]  = {(const float*)d_in[4],  (const float*)d_in[10]};
    const float* vW[2]  = {(const float*)d_in[5],  (const float*)d_in[11]};
    const float* f1[2]  = {(const float*)d_in[6],  (const float*)d_in[12]};
    const float* f2[2]  = {(const float*)d_in[7],  (const float*)d_in[13]};
    const float* tau[2] = {(const float*)d_in[8],  (const float*)d_in[14]};
    const float* hW = (const float*)d_in[15];
    const float* ls = (const float*)d_in[16];
    float* out = (float*)d_out;

    embed_kernel<<<98, 512>>>(x, eW, pos);
    for (int l = 0; l < 2; l++) {
        gemmA_kernel<0><<<dim3(49, 6), 128>>>(qW[l], kW[l], vW[l], nullptr);
        gemmA_kernel<1><<<dim3(7, 4, 8), 128>>>(nullptr, nullptr, nullptr, nullptr);
        attnout_kernel<<<dim3(13, 8), 512>>>();
        gemmA_kernel<2><<<dim3(49, 4), 128>>>(f1[l], nullptr, nullptr, tau[l]);
        ff2_kernel<<<98, 512>>>(f2[l]);
    }
    pool_kernel<<<8, 512>>>();
    head_kernel<<<dim3(4, 8), 256>>>(hW, ls, out);
}

// round 7
// speedup vs baseline: 1.2644x; 1.0077x over previous
#include <cuda_runtime.h>

#define DEV_INLINE __device__ __forceinline__

namespace {
constexpr int Bb = 8, N_ = 196, D_ = 128, DFF_ = 256, C_ = 1000;
constexpr int M_ = Bb * N_;            // 1568 total rows
constexpr float NEG = -1e30f;
}

__device__ float g_h[M_ * D_];
__device__ float g_xn[M_ * D_];
__device__ float g_q[M_ * D_];
__device__ float g_k[M_ * D_];
__device__ float g_vt[Bb * D_ * N_];   // v transposed per batch: [b][d][n]
__device__ float g_sc[Bb * N_ * N_];   // attention scores
__device__ float g_ff[M_ * DFF_];
__device__ float g_pool[Bb * D_];

DEV_INLINE float warpMax(float v) {
#pragma unroll
    for (int m = 16; m > 0; m >>= 1)
        v = fmaxf(v, __shfl_xor_sync(0xffffffffu, v, m));
    return v;
}

// ============================================================
// GEMM (split-K2): out[m,n] = max_k(A[m,k]+W[n,k]), K=128.
// 256 threads = 2 groups of 128; group g covers K-half g.
// BM=32, BN=64, BK=32, per-thread 4x4.
// MODE 0: qkv fused; MODE 1: scores; MODE 2: ff1 (+tau)
// ============================================================
template <int MODE>
__global__ void __launch_bounds__(256) gemmA_kernel(
    const float* __restrict__ W0, const float* __restrict__ W1,
    const float* __restrict__ W2, const float* __restrict__ tau) {
    __shared__ __align__(16) float As[2][32][36];
    __shared__ __align__(16) float Ws[2][32][68];
    __shared__ __align__(16) float red[32][68];
    const int tid = threadIdx.x;
    const int wg = tid >> 7;
    const int wtid = tid & 127;
    const int m0 = blockIdx.x * 32;
    const int n0 = blockIdx.y * 64;

    const float* Ap;
    const float* Wp;
    if (MODE == 0) {
        Ap = g_xn;
        int sec = n0 >> 7;
        Wp = (sec == 0 ? W0 : (sec == 1 ? W1 : W2)) + (n0 & 127) * 128;
    } else if (MODE == 1) {
        int b = blockIdx.z;
        Ap = g_q + b * N_ * D_;
        Wp = g_k + b * N_ * D_;
    } else {
        Ap = g_xn;
        Wp = W0 + n0 * 128;
    }

    const int kq = wtid & 7, l = wtid >> 3;   // loader: 8 quads x 16 rows
    float acc[4][4];
#pragma unroll
    for (int r = 0; r < 4; r++)
#pragma unroll
        for (int c = 0; c < 4; c++) acc[r][c] = NEG;
    const int r0 = (wtid >> 4) * 4, c0 = (wtid & 15) * 4;

#pragma unroll
    for (int t = 0; t < 2; t++) {
        int k0 = wg * 64 + t * 32;
        // A tile 32x32 (rows l, l+16)
#pragma unroll
        for (int p = 0; p < 2; p++) {
            int row = l + p * 16;
            float4 av;
            if (MODE == 1 && (m0 + row) >= N_) av = make_float4(NEG, NEG, NEG, NEG);
            else av = *(const float4*)(Ap + (m0 + row) * 128 + k0 + kq * 4);
            As[wg][kq * 4 + 0][row] = av.x; As[wg][kq * 4 + 1][row] = av.y;
            As[wg][kq * 4 + 2][row] = av.z; As[wg][kq * 4 + 3][row] = av.w;
        }
        // W tile 64x32
#pragma unroll
        for (int p = 0; p < 4; p++) {
            int nl = l + p * 16;
            float4 wv;
            if (MODE == 1 && (n0 + nl) >= N_) wv = make_float4(NEG, NEG, NEG, NEG);
            else {
                int wrow = (MODE == 1) ? (n0 + nl) : nl;
                wv = *(const float4*)(Wp + wrow * 128 + k0 + kq * 4);
            }
            Ws[wg][kq * 4 + 0][nl] = wv.x; Ws[wg][kq * 4 + 1][nl] = wv.y;
            Ws[wg][kq * 4 + 2][nl] = wv.z; Ws[wg][kq * 4 + 3][nl] = wv.w;
        }
        __syncthreads();
#pragma unroll
        for (int kk = 0; kk < 32; kk++) {
            float4 a = *(const float4*)&As[wg][kk][r0];
            float4 w = *(const float4*)&Ws[wg][kk][c0];
            float ar[4] = {a.x, a.y, a.z, a.w};
            float wr[4] = {w.x, w.y, w.z, w.w};
#pragma unroll
            for (int r = 0; r < 4; r++)
#pragma unroll
                for (int c = 0; c < 4; c++)
                    acc[r][c] = fmaxf(acc[r][c], ar[r] + wr[c]);
        }
        __syncthreads();
    }

    if (wg == 1) {
#pragma unroll
        for (int r = 0; r < 4; r++)
            *(float4*)&red[r0 + r][c0] =
                make_float4(acc[r][0], acc[r][1], acc[r][2], acc[r][3]);
    }
    __syncthreads();
    if (wg == 1) return;

#pragma unroll
    for (int r = 0; r < 4; r++) {
        float4 rv = *(const float4*)&red[r0 + r][c0];
        acc[r][0] = fmaxf(acc[r][0], rv.x);
        acc[r][1] = fmaxf(acc[r][1], rv.y);
        acc[r][2] = fmaxf(acc[r][2], rv.z);
        acc[r][3] = fmaxf(acc[r][3], rv.w);
    }

    if (MODE == 0) {
#pragma unroll
        for (int r = 0; r < 4; r++) {
            int gm = m0 + r0 + r;
            int b = gm / 196, i = gm - b * 196;
#pragma unroll
            for (int c = 0; c < 4; c++) {
                int gn = n0 + c0 + c;
                float v = acc[r][c];
                if (gn < 128)       g_q[gm * 128 + gn] = v;
                else if (gn < 256)  g_k[gm * 128 + (gn - 128)] = v;
                else                g_vt[(b * 128 + (gn - 256)) * N_ + i] = v;
            }
        }
    } else if (MODE == 1) {
        int b = blockIdx.z;
        float* out = g_sc + b * N_ * N_;
#pragma unroll
        for (int r = 0; r < 4; r++) {
            int i = m0 + r0 + r;
            if (i < N_) {
#pragma unroll
                for (int c = 0; c < 4; c++) {
                    int j = n0 + c0 + c;
                    if (j < N_) out[i * N_ + j] = acc[r][c];
                }
            }
        }
    } else {
        float tv = tau[0];
#pragma unroll
        for (int r = 0; r < 4; r++) {
            int gm = m0 + r0 + r;
#pragma unroll
            for (int c = 0; c < 4; c++)
                g_ff[gm * 256 + n0 + c0 + c] = fmaxf(acc[r][c], tv);
        }
    }
}

// ============================================================
// Row-fused config (split-K4): 1024 threads = 4 groups of 256.
// BM=16, BN=128, BK=16. Tile buffers aliased with reduction
// buffers (dead after mainloop) to stay under 48KB static smem.
// ============================================================
constexpr int AS_BYTES = 4 * 16 * 18 * 4;        // 4608
constexpr int WS_BYTES = 4 * 16 * 132 * 4;       // 33792
constexpr int SBUF_BYTES = AS_BYTES + WS_BYTES;  // 38400 (red 3*16*132*4=25344 fits)

DEV_INLINE void innerB16(const float (&As)[16][18], const float (&Ws)[16][132],
                         float (&acc)[2][4], int r0, int c0) {
#pragma unroll
    for (int kk = 0; kk < 16; kk++) {
        float a0 = As[kk][r0], a1 = As[kk][r0 + 1];
        float4 w = *(const float4*)&Ws[kk][c0];
        acc[0][0] = fmaxf(acc[0][0], a0 + w.x);
        acc[0][1] = fmaxf(acc[0][1], a0 + w.y);
        acc[0][2] = fmaxf(acc[0][2], a0 + w.z);
        acc[0][3] = fmaxf(acc[0][3], a0 + w.w);
        acc[1][0] = fmaxf(acc[1][0], a1 + w.x);
        acc[1][1] = fmaxf(acc[1][1], a1 + w.y);
        acc[1][2] = fmaxf(acc[1][2], a1 + w.z);
        acc[1][3] = fmaxf(acc[1][3], a1 + w.w);
    }
}
DEV_INLINE void innerB16rm(const float (&As)[16][18], const float (&Ws)[16][132],
                           float (&acc)[2][4], float (&rm)[2], int r0, int c0) {
#pragma unroll
    for (int kk = 0; kk < 16; kk++) {
        float a0 = As[kk][r0], a1 = As[kk][r0 + 1];
        rm[0] = fmaxf(rm[0], a0); rm[1] = fmaxf(rm[1], a1);
        float4 w = *(const float4*)&Ws[kk][c0];
        acc[0][0] = fmaxf(acc[0][0], a0 + w.x);
        acc[0][1] = fmaxf(acc[0][1], a0 + w.y);
        acc[0][2] = fmaxf(acc[0][2], a0 + w.z);
        acc[0][3] = fmaxf(acc[0][3], a0 + w.w);
        acc[1][0] = fmaxf(acc[1][0], a1 + w.x);
        acc[1][1] = fmaxf(acc[1][1], a1 + w.y);
        acc[1][2] = fmaxf(acc[1][2], a1 + w.z);
        acc[1][3] = fmaxf(acc[1][3], a1 + w.w);
    }
}

// embed: patchify + trop_mm(embed_W) + pos + pnorm -> g_h, g_xn. K=256 = 16 tiles.
__global__ void __launch_bounds__(1024) embed_kernel(
    const float* __restrict__ x, const float* __restrict__ eW,
    const float* __restrict__ pos) {
    __shared__ __align__(16) char sbuf[SBUF_BYTES];
    float (*As)[16][18]  = reinterpret_cast<float(*)[16][18]>(sbuf);
    float (*Ws)[16][132] = reinterpret_cast<float(*)[16][132]>(sbuf + AS_BYTES);
    float (*red)[16][132] = reinterpret_cast<float(*)[16][132]>(sbuf);  // alias (post-loop)
    const int tid = threadIdx.x;
    const int wg = tid >> 8;
    const int wtid = tid & 255;
    const int m0 = blockIdx.x * 16;
    const int r0 = (wtid >> 5) * 2, c0 = (wtid & 31) * 4;
    float acc[2][4];
#pragma unroll
    for (int r = 0; r < 2; r++)
#pragma unroll
        for (int c = 0; c < 4; c++) acc[r][c] = NEG;

#pragma unroll
    for (int t = 0; t < 4; t++) {
        int k0 = (t * 4 + wg) * 16;
        if (wtid < 64) {
            int l = wtid >> 2, kq = wtid & 3;
            int gm = m0 + l;
            int b = gm / 196, n = gm - b * 196;
            int gy = n / 14, gx = n - gy * 14;
            int k = k0 + kq * 4;
            int py = k >> 4, px = k & 15;
            float4 av = *(const float4*)(x + b * 50176 + (gy * 16 + py) * 224 + gx * 16 + px);
            As[wg][kq * 4 + 0][l] = av.x; As[wg][kq * 4 + 1][l] = av.y;
            As[wg][kq * 4 + 2][l] = av.z; As[wg][kq * 4 + 3][l] = av.w;
        }
        {
            int kq = wtid & 3, base = wtid >> 2;   // base 0..63
#pragma unroll
            for (int p = 0; p < 2; p++) {
                int nl = base + p * 64;
                float4 wv = *(const float4*)(eW + nl * 256 + k0 + kq * 4);
                Ws[wg][kq * 4 + 0][nl] = wv.x; Ws[wg][kq * 4 + 1][nl] = wv.y;
                Ws[wg][kq * 4 + 2][nl] = wv.z; Ws[wg][kq * 4 + 3][nl] = wv.w;
            }
        }
        __syncthreads();
        innerB16(As[wg], Ws[wg], acc, r0, c0);
        __syncthreads();
    }

    if (wg > 0) {
#pragma unroll
        for (int r = 0; r < 2; r++)
            *(float4*)&red[wg - 1][r0 + r][c0] =
                make_float4(acc[r][0], acc[r][1], acc[r][2], acc[r][3]);
    }
    __syncthreads();
    if (wg > 0) return;

#pragma unroll
    for (int r = 0; r < 2; r++) {
#pragma unroll
        for (int g = 0; g < 3; g++) {
            float4 rv = *(const float4*)&red[g][r0 + r][c0];
            acc[r][0] = fmaxf(acc[r][0], rv.x);
            acc[r][1] = fmaxf(acc[r][1], rv.y);
            acc[r][2] = fmaxf(acc[r][2], rv.z);
            acc[r][3] = fmaxf(acc[r][3], rv.w);
        }
        int gm = m0 + r0 + r;
        int n = gm % 196;
        float h[4];
#pragma unroll
        for (int c = 0; c < 4; c++) h[c] = acc[r][c] + pos[n * 128 + c0 + c];
        float dm = warpMax(fmaxf(fmaxf(h[0], h[1]), fmaxf(h[2], h[3])));
        int base = gm * 128 + c0;
#pragma unroll
        for (int c = 0; c < 4; c++) {
            g_h[base + c] = h[c];
            g_xn[base + c] = h[c] - dm;
        }
    }
}

// attnout: o[i,d]=max_j(sc[i,j]+vt[d,j])-rowmax; pnorm; residual; pnorm.
// K=196 -> 13 tiles of 16; tile tt=t*4+wg (tt>=13 skipped).
__global__ void __launch_bounds__(1024) attnout_kernel() {
    __shared__ __align__(16) char sbuf[SBUF_BYTES];
    float (*As)[16][18]  = reinterpret_cast<float(*)[16][18]>(sbuf);
    float (*Ws)[16][132] = reinterpret_cast<float(*)[16][132]>(sbuf + AS_BYTES);
    float (*red)[16][132] = reinterpret_cast<float(*)[16][132]>(sbuf);
    __shared__ float redrm[3][16];
    const int tid = threadIdx.x;
    const int wg = tid >> 8;
    const int wtid = tid & 255;
    const int b = blockIdx.y;
    const int m0 = blockIdx.x * 16;
    const float* Ap = g_sc + b * N_ * N_;
    const float* Vp = g_vt + b * D_ * N_;
    const int r0 = (wtid >> 5) * 2, c0 = (wtid & 31) * 4;
    float acc[2][4];
    float rm[2] = {NEG, NEG};
#pragma unroll
    for (int r = 0; r < 2; r++)
#pragma unroll
        for (int c = 0; c < 4; c++) acc[r][c] = NEG;

#pragma unroll
    for (int t = 0; t < 4; t++) {
        int j0 = (t * 4 + wg) * 16;
        bool tvalid = j0 < N_;
        if (tvalid) {
            if (wtid < 64) {
                int l = wtid >> 2, kq = wtid & 3;
                int gm = m0 + l;
                int j = j0 + kq * 4;
                float4 av = (gm < N_ && j < N_)
                                ? *(const float4*)(Ap + gm * N_ + j)
                                : make_float4(NEG, NEG, NEG, NEG);
                As[wg][kq * 4 + 0][l] = av.x; As[wg][kq * 4 + 1][l] = av.y;
                As[wg][kq * 4 + 2][l] = av.z; As[wg][kq * 4 + 3][l] = av.w;
            }
            {
                int kq = wtid & 3, base = wtid >> 2;
                int j = j0 + kq * 4;
#pragma unroll
                for (int p = 0; p < 2; p++) {
                    int d = base + p * 64;
                    float4 vv = (j < N_) ? *(const float4*)(Vp + d * N_ + j)
                                         : make_float4(NEG, NEG, NEG, NEG);
                    Ws[wg][kq * 4 + 0][d] = vv.x; Ws[wg][kq * 4 + 1][d] = vv.y;
                    Ws[wg][kq * 4 + 2][d] = vv.z; Ws[wg][kq * 4 + 3][d] = vv.w;
                }
            }
        }
        __syncthreads();
        if (tvalid) innerB16rm(As[wg], Ws[wg], acc, rm, r0, c0);
        __syncthreads();
    }

    if (wg > 0) {
#pragma unroll
        for (int r = 0; r < 2; r++) {
            *(float4*)&red[wg - 1][r0 + r][c0] =
                make_float4(acc[r][0], acc[r][1], acc[r][2], acc[r][3]);
            if ((wtid & 31) == 0) redrm[wg - 1][r0 + r] = rm[r];
        }
    }
    __syncthreads();
    if (wg > 0) return;

#pragma unroll
    for (int r = 0; r < 2; r++) {
        int i = m0 + r0 + r;
        if (i < N_) {
            float frm = rm[r];
#pragma unroll
            for (int g = 0; g < 3; g++) {
                frm = fmaxf(frm, redrm[g][r0 + r]);
                float4 rv = *(const float4*)&red[g][r0 + r][c0];
                acc[r][0] = fmaxf(acc[r][0], rv.x);
                acc[r][1] = fmaxf(acc[r][1], rv.y);
                acc[r][2] = fmaxf(acc[r][2], rv.z);
                acc[r][3] = fmaxf(acc[r][3], rv.w);
            }
            float o[4];
#pragma unroll
            for (int c = 0; c < 4; c++) o[c] = acc[r][c] - frm;
            float dm = warpMax(fmaxf(fmaxf(o[0], o[1]), fmaxf(o[2], o[3])));
            int base = (b * 196 + i) * 128 + c0;
            float nx[4];
#pragma unroll
            for (int c = 0; c < 4; c++)
                nx[c] = fmaxf(g_h[base + c], o[c] - dm);
            float dm2 = warpMax(fmaxf(fmaxf(nx[0], nx[1]), fmaxf(nx[2], nx[3])));
#pragma unroll
            for (int c = 0; c < 4; c++) {
                g_h[base + c] = nx[c];
                g_xn[base + c] = nx[c] - dm2;
            }
        }
    }
}

// ff2: trop_mm(g_ff, f2W), K=256 = 16 tiles; pnorm; residual; pnorm.
__global__ void __launch_bounds__(1024) ff2_kernel(const float* __restrict__ W) {
    __shared__ __align__(16) char sbuf[SBUF_BYTES];
    float (*As)[16][18]  = reinterpret_cast<float(*)[16][18]>(sbuf);
    float (*Ws)[16][132] = reinterpret_cast<float(*)[16][132]>(sbuf + AS_BYTES);
    float (*red)[16][132] = reinterpret_cast<float(*)[16][132]>(sbuf);
    const int tid = threadIdx.x;
    const int wg = tid >> 8;
    const int wtid = tid & 255;
    const int m0 = blockIdx.x * 16;
    const int r0 = (wtid >> 5) * 2, c0 = (wtid & 31) * 4;
    float acc[2][4];
#pragma unroll
    for (int r = 0; r < 2; r++)
#pragma unroll
        for (int c = 0; c < 4; c++) acc[r][c] = NEG;

#pragma unroll
    for (int t = 0; t < 4; t++) {
        int k0 = (t * 4 + wg) * 16;
        if (wtid < 64) {
            int l = wtid >> 2, kq = wtid & 3;
            float4 av = *(const float4*)(g_ff + (m0 + l) * 256 + k0 + kq * 4);
            As[wg][kq * 4 + 0][l] = av.x; As[wg][kq * 4 + 1][l] = av.y;
            As[wg][kq * 4 + 2][l] = av.z; As[wg][kq * 4 + 3][l] = av.w;
        }
        {
            int kq = wtid & 3, base = wtid >> 2;
#pragma unroll
            for (int p = 0; p < 2; p++) {
                int nl = base + p * 64;
                float4 wv = *(const float4*)(W + nl * 256 + k0 + kq * 4);
                Ws[wg][kq * 4 + 0][nl] = wv.x; Ws[wg][kq * 4 + 1][nl] = wv.y;
                Ws[wg][kq * 4 + 2][nl] = wv.z; Ws[wg][kq * 4 + 3][nl] = wv.w;
            }
        }
        __syncthreads();
        innerB16(As[wg], Ws[wg], acc, r0, c0);
        __syncthreads();
    }

    if (wg > 0) {
#pragma unroll
        for (int r = 0; r < 2; r++)
            *(float4*)&red[wg - 1][r0 + r][c0] =
                make_float4(acc[r][0], acc[r][1], acc[r][2], acc[r][3]);
    }
    __syncthreads();
    if (wg > 0) return;

#pragma unroll
    for (int r = 0; r < 2; r++) {
#pragma unroll
        for (int g = 0; g < 3; g++) {
            float4 rv = *(const float4*)&red[g][r0 + r][c0];
            acc[r][0] = fmaxf(acc[r][0], rv.x);
            acc[r][1] = fmaxf(acc[r][1], rv.y);
            acc[r][2] = fmaxf(acc[r][2], rv.z);
            acc[r][3] = fmaxf(acc[r][3], rv.w);
        }
        int gm = m0 + r0 + r;
        float dm = warpMax(fmaxf(fmaxf(acc[r][0], acc[r][1]), fmaxf(acc[r][2], acc[r][3])));
        int base = gm * 128 + c0;
        float nx[4];
#pragma unroll
        for (int c = 0; c < 4; c++)
            nx[c] = fmaxf(g_h[base + c], acc[r][c] - dm);
        float dm2 = warpMax(fmaxf(fmaxf(nx[0], nx[1]), fmaxf(nx[2], nx[3])));
#pragma unroll
        for (int c = 0; c < 4; c++) {
            g_h[base + c] = nx[c];
            g_xn[base + c] = nx[c] - dm2;
        }
    }
}

__global__ void __launch_bounds__(512) pool_kernel() {
    __shared__ float sm[4][128];
    int b = blockIdx.x;
    int d = threadIdx.x & 127;
    int q = threadIdx.x >> 7;
    float m = NEG;
    for (int n = q; n < N_; n += 4)
        m = fmaxf(m, g_h[(b * N_ + n) * D_ + d]);
    sm[q][d] = m;
    __syncthreads();
    if (q == 0) {
        m = fmaxf(fmaxf(sm[0][d], sm[1][d]), fmaxf(sm[2][d], sm[3][d]));
        g_pool[b * D_ + d] = m;
    }
}

__global__ void __launch_bounds__(256) head_kernel(
    const float* __restrict__ hW, const float* __restrict__ ls,
    float* __restrict__ out) {
    __shared__ float sp[128];
    const int b = blockIdx.y;
    const int tid = threadIdx.x;
    if (tid < 128) sp[tid] = g_pool[b * 128 + tid];
    __syncthreads();
    int c = blockIdx.x * 256 + tid;
    if (c < C_) {
        float acc = NEG;
#pragma unroll 8
        for (int d = 0; d < 128; d += 4) {
            float4 w = *(const float4*)(hW + c * 128 + d);
            acc = fmaxf(acc, sp[d + 0] + w.x);
            acc = fmaxf(acc, sp[d + 1] + w.y);
            acc = fmaxf(acc, sp[d + 2] + w.z);
            acc = fmaxf(acc, sp[d + 3] + w.w);
        }
        out[b * C_ + c] = acc * ls[0];
    }
}

extern "C" void kernel_launch(void* const* d_in, const int* in_sizes, int n_in,
                              void* d_out, int out_size) {
    const float* x   = (const float*)d_in[0];
    const float* eW  = (const float*)d_in[1];
    const float* pos = (const float*)d_in[2];
    const float* qW[2]  = {(const float*)d_in[3],  (const float*)d_in[9]};
    const float* kW[2]  = {(const float*)d_in[4],  (const float*)d_in[10]};
    const float* vW[2]  = {(const float*)d_in[5],  (const float*)d_in[11]};
    const float* f1[2]  = {(const float*)d_in[6],  (const float*)d_in[12]};
    const float* f2[2]  = {(const float*)d_in[7],  (const float*)d_in[13]};
    const float* tau[2] = {(const float*)d_in[8],  (const float*)d_in[14]};
    const float* hW = (const float*)d_in[15];
    const float* ls = (const float*)d_in[16];
    float* out = (float*)d_out;

    embed_kernel<<<98, 1024>>>(x, eW, pos);
    for (int l = 0; l < 2; l++) {
        gemmA_kernel<0><<<dim3(49, 6), 256>>>(qW[l], kW[l], vW[l], nullptr);
        gemmA_kernel<1><<<dim3(7, 4, 8), 256>>>(nullptr, nullptr, nullptr, nullptr);
        attnout_kernel<<<dim3(13, 8), 1024>>>();
        gemmA_kernel<2><<<dim3(49, 4), 256>>>(f1[l], nullptr, nullptr, tau[l]);
        ff2_kernel<<<98, 1024>>>(f2[l]);
    }
    pool_kernel<<<8, 512>>>();
    head_kernel<<<dim3(4, 8), 256>>>(hW, ls, out);
}